// round 6
// baseline (speedup 1.0000x reference)
#include <cuda_runtime.h>
#include <cuda_bf16.h>
#include <math.h>
#include <stdint.h>

#define B_ 8
#define N_ 19
#define T_ 1000
#define D_ 512
#define ALPHA 0.05f
#define LN_EPS 1e-5f
#define ROW_EPS 1e-6f

#define NGRAPH (B_ * T_)       // 8000
#define NROWS (NGRAPH * N_)    // 152000 = 2375 * 64 exactly
#define MTILES 2375
#define KCHUNKS 8              // 512/64
#define ATILE_BYTES 8192       // 64 rows x 64 k x bf16 (swizzled)
#define BTILE_BYTES 65536      // 512 n  x 64 k x bf16 (swizzled)
#define STAGE_BYTES 81920      // A hi+lo (16KB) + B (64KB)
#define GEMM_SMEM_DYN (2 * STAGE_BYTES + 1024)
#define YS 516                 // y staging row stride (floats)

// ---------------- scratch (__device__ globals; no runtime alloc) ------------
__device__ __align__(16) unsigned char g_ahi[(size_t)MTILES * KCHUNKS * ATILE_BYTES];
__device__ __align__(16) unsigned char g_alo[(size_t)MTILES * KCHUNKS * ATILE_BYTES];
__device__ __align__(16) unsigned char g_bhi[2 * KCHUNKS * BTILE_BYTES];
__device__ __align__(16) unsigned char g_blo[2 * KCHUNKS * BTILE_BYTES];
__device__ float g_adjn[(size_t)NGRAPH * N_ * N_];
__device__ float g_state[(size_t)NROWS * D_];

// ---------------- helpers ---------------------------------------------------
__device__ __forceinline__ uint32_t swz(uint32_t o) { return o ^ ((o >> 3) & 0x70); }

__device__ __forceinline__ uint32_t smem_u32(const void* p) {
    uint32_t a;
    asm("{ .reg .u64 t; cvta.to.shared.u64 t, %1; cvt.u32.u64 %0, t; }" : "=r"(a) : "l"(p));
    return a;
}
__device__ __forceinline__ void bulk_g2s(uint32_t dst, const void* src,
                                         uint32_t bytes, uint32_t mbar) {
    asm volatile(
        "cp.async.bulk.shared::cta.global.mbarrier::complete_tx::bytes [%0], [%1], %2, [%3];"
        :: "r"(dst), "l"(src), "r"(bytes), "r"(mbar) : "memory");
}
#define MBAR_INIT(a, c) asm volatile("mbarrier.init.shared.b64 [%0], %1;" :: "r"(a), "r"(c) : "memory")
#define MBAR_EXPECT(a, b) asm volatile("mbarrier.arrive.expect_tx.shared.b64 _, [%0], %1;" :: "r"(a), "r"(b) : "memory")
#define MBAR_WAIT(addr, ph) do {                                                      \
    asm volatile(                                                                     \
        "{\n\t.reg .pred P;\n\t"                                                      \
        "WL_%=:\n\t"                                                                  \
        "mbarrier.try_wait.parity.acquire.cta.shared::cta.b64 P, [%0], %1, 0x989680;\n\t" \
        "@P bra.uni WD_%=;\n\t"                                                       \
        "bra.uni WL_%=;\n\t"                                                          \
        "WD_%=:\n\t}"                                                                 \
        :: "r"(addr), "r"(ph) : "memory");                                            \
} while (0)

#define LDX4(r, a)                                                                    \
    asm volatile("ldmatrix.sync.aligned.m8n8.x4.shared.b16 {%0,%1,%2,%3}, [%4];"      \
        : "=r"((r)[0]), "=r"((r)[1]), "=r"((r)[2]), "=r"((r)[3]) : "r"(a))

#define MMA(c, a, b0v, b1v)                                                           \
    asm volatile("mma.sync.aligned.m16n8k16.row.col.f32.bf16.bf16.f32 "               \
        "{%0,%1,%2,%3},{%4,%5,%6,%7},{%8,%9},{%0,%1,%2,%3};"                          \
        : "+f"((c)[0]), "+f"((c)[1]), "+f"((c)[2]), "+f"((c)[3])                      \
        : "r"((a)[0]), "r"((a)[1]), "r"((a)[2]), "r"((a)[3]), "r"(b0v), "r"(b1v))

// ---------------- stage 1: adjacency softplus + row-normalize ---------------
__global__ __launch_bounds__(128)
void adj_kernel(const float* __restrict__ adjacency,
                const float* __restrict__ edge_w, const float* __restrict__ edge_b)
{
    __shared__ float s[N_][N_];
    int g = blockIdx.x, tid = threadIdx.x;
    float ew = edge_w[0], eb = edge_b[0];
    const float* a = adjacency + (size_t)g * N_ * N_;
    for (int i = tid; i < N_ * N_; i += 128) {
        float v = fmaf(a[i], ew, eb);
        ((float*)s)[i] = fmaxf(v, 0.0f) + log1pf(expf(-fabsf(v)));
    }
    __syncthreads();
    if (tid < N_) {
        float sum = 0.0f;
        #pragma unroll
        for (int j = 0; j < N_; j++) sum += s[tid][j];
        float inv = 1.0f / (sum + ROW_EPS);
        #pragma unroll
        for (int j = 0; j < N_; j++) s[tid][j] *= inv;
    }
    __syncthreads();
    for (int i = tid; i < N_ * N_; i += 128)
        g_adjn[(size_t)g * N_ * N_ + i] = ((float*)s)[i];
}

// ---------------- stage 2: W -> bf16 hi/lo W^T blocks (n-major, swizzled) ---
// block index = layer*8 + kchunk; inside: 512 n-rows x 128B (64 k), swizzled.
__global__ __launch_bounds__(256)
void wconv_kernel(const float* __restrict__ W)
{
    int p = blockIdx.x * 256 + threadIdx.x;   // 2*512*64 tasks
    if (p >= 2 * 512 * 64) return;
    int l = p >> 15;
    int rem = p & 32767;
    int n = rem >> 6;
    int k8 = rem & 63;
    int k0 = k8 * 8;
    const float* src = W + (size_t)l * D_ * D_ + n;
    union { uint4 q; __nv_bfloat16 h[8]; } H, L;
    #pragma unroll
    for (int i = 0; i < 8; i++) {
        float w = src[(size_t)(k0 + i) * D_];
        H.h[i] = __float2bfloat16(w);
        L.h[i] = __float2bfloat16(w - __bfloat162float(H.h[i]));
    }
    int kchunk = k0 >> 6, kl = k0 & 63;
    size_t blk = (size_t)l * KCHUNKS + kchunk;
    uint32_t off = swz((uint32_t)(n * 128 + kl * 2));
    *(uint4*)(g_bhi + blk * BTILE_BYTES + off) = H.q;
    *(uint4*)(g_blo + blk * BTILE_BYTES + off) = L.q;
}

// ---------------- stage 3: mixing + bf16 split -> swizzled A tiles ----------
__global__ __launch_bounds__(256)
void mix_kernel(const float* __restrict__ src, int transposed)
{
    __shared__ float xs[N_][D_];
    __shared__ float sadj[N_][N_];
    int g = blockIdx.x, tid = threadIdx.x;
    for (int i = tid; i < N_ * N_; i += 256)
        ((float*)sadj)[i] = g_adjn[(size_t)g * N_ * N_ + i];
    long tb = 0;
    if (transposed) {
        int bb = g / T_, tt = g - bb * T_;
        tb = (long)bb * N_ * T_ * D_ + (long)tt * D_;
    }
    for (int idx = tid; idx < N_ * D_; idx += 256) {
        int n = idx >> 9, d = idx & (D_ - 1);
        xs[n][d] = transposed ? src[tb + (long)n * T_ * D_ + d]
                              : src[((long)g * N_ + n) * D_ + d];
    }
    __syncthreads();
    for (int task = tid; task < N_ * 64; task += 256) {
        int n = task >> 6, k8 = task & 63, d0 = k8 << 3;
        float m[8];
        #pragma unroll
        for (int i = 0; i < 8; i++) m[i] = (1.0f - ALPHA) * xs[n][d0 + i];
        #pragma unroll
        for (int j = 0; j < N_; j++) {
            float a = ALPHA * sadj[n][j];
            #pragma unroll
            for (int i = 0; i < 8; i++) m[i] = fmaf(a, xs[j][d0 + i], m[i]);
        }
        union { uint4 q; __nv_bfloat16 h[8]; } H, L;
        #pragma unroll
        for (int i = 0; i < 8; i++) {
            H.h[i] = __float2bfloat16(m[i]);
            L.h[i] = __float2bfloat16(m[i] - __bfloat162float(H.h[i]));
        }
        int r = g * N_ + n;
        int mt = r >> 6, rl = r & 63;
        size_t blk = (size_t)mt * KCHUNKS + (k8 >> 3);
        uint32_t off = swz((uint32_t)(rl * 128 + (k8 & 7) * 16));
        *(uint4*)(g_ahi + blk * ATILE_BYTES + off) = H.q;
        *(uint4*)(g_alo + blk * ATILE_BYTES + off) = L.q;
    }
}

// ---------------- stage 4: fused GEMM (2-pass 3-term split) + LN + GELU -----
// CTA tile 64 rows x 512 cols. 8 warps: wm = wid>>2 (2), wn = wid&3 (4);
// warp tile 32x128, acc[2][16][4]. Pass 0 (stages 0..7): Ahi*Bhi + Alo*Bhi.
// Pass 1 (stages 8..15): Ahi*Blo. Epilogue: bias -> smem y, +residual, LN,
// exact GELU, final store. No intermediate y in global memory.
__global__ __launch_bounds__(256, 1)
void gemm_kernel(const unsigned char* __restrict__ gAh,
                 const unsigned char* __restrict__ gAl,
                 const unsigned char* __restrict__ gBh,
                 const unsigned char* __restrict__ gBl,
                 const float* __restrict__ res, int res_trans,
                 float* __restrict__ dst, int dst_trans,
                 const float* __restrict__ gamma, const float* __restrict__ beta,
                 const float* __restrict__ bias, int layer)
{
    extern __shared__ unsigned char smraw[];
    __shared__ __align__(8) unsigned long long s_mbar[2];
    __shared__ float sBias[D_], sGam[D_], sBet[D_];

    const int tid = threadIdx.x, wid = tid >> 5, lane = tid & 31;
    const int wm = wid >> 2, wn = wid & 3;
    const int mtile = blockIdx.x;

    const uint32_t base = (smem_u32(smraw) + 1023) & ~1023u;
    const uint32_t mb0 = smem_u32(&s_mbar[0]);
    const uint32_t mb1 = mb0 + 8;
    if (tid == 0) { MBAR_INIT(mb0, 1); MBAR_INIT(mb1, 1); }
    for (int i = tid; i < D_; i += 256) {
        sBias[i] = bias[layer * D_ + i];
        sGam[i] = gamma[layer * D_ + i];
        sBet[i] = beta[layer * D_ + i];
    }
    __syncthreads();

    const unsigned char* pAh = gAh + (size_t)mtile * KCHUNKS * ATILE_BYTES;
    const unsigned char* pAl = gAl + (size_t)mtile * KCHUNKS * ATILE_BYTES;

    // per-lane ldmatrix address constants
    const uint32_t a_rowoff = (wm * 32 + (lane & 15)) * 128;
    const uint32_t a_klane = (uint32_t)(lane >> 4) << 4;
    const uint32_t b_rowoff = (wn * 128 + ((lane >> 4) << 3) + (lane & 7)) * 128;
    const uint32_t b_klane = (uint32_t)((lane >> 3) & 1) << 4;
    const uint32_t cswz = (uint32_t)(lane & 7) << 4;

    float acc[2][16][4];
    #pragma unroll
    for (int ms = 0; ms < 2; ms++)
        #pragma unroll
        for (int ns = 0; ns < 16; ns++)
            #pragma unroll
            for (int q = 0; q < 4; q++) acc[ms][ns][q] = 0.0f;

    // prologue: stage 0 (pass 0, kc 0)
    if (tid == 0) {
        MBAR_EXPECT(mb0, 81920u);
        bulk_g2s(base,         pAh, ATILE_BYTES, mb0);
        bulk_g2s(base + 8192,  pAl, ATILE_BYTES, mb0);
        bulk_g2s(base + 16384, gBh, BTILE_BYTES, mb0);
    }

    for (int s = 0; s < 16; s++) {
        MBAR_WAIT((s & 1) ? mb1 : mb0, (s >> 1) & 1);
        __syncthreads();
        if (tid == 0 && s + 1 < 16) {
            const int sn = s + 1, kn = sn & 7;
            const uint32_t st = base + (sn & 1) * STAGE_BYTES;
            const uint32_t mb = (sn & 1) ? mb1 : mb0;
            if (sn < 8) {
                MBAR_EXPECT(mb, 81920u);
                bulk_g2s(st,         pAh + (size_t)kn * ATILE_BYTES, ATILE_BYTES, mb);
                bulk_g2s(st + 8192,  pAl + (size_t)kn * ATILE_BYTES, ATILE_BYTES, mb);
                bulk_g2s(st + 16384, gBh + (size_t)kn * BTILE_BYTES, BTILE_BYTES, mb);
            } else {
                MBAR_EXPECT(mb, 73728u);
                bulk_g2s(st,         pAh + (size_t)kn * ATILE_BYTES, ATILE_BYTES, mb);
                bulk_g2s(st + 16384, gBl + (size_t)kn * BTILE_BYTES, BTILE_BYTES, mb);
            }
        }
        const uint32_t st = base + (s & 1) * STAGE_BYTES;
        const uint32_t sA = st, sA2 = st + 8192, sB = st + 16384;
        const bool two = (s < 8);

        #pragma unroll
        for (int ks = 0; ks < 4; ks++) {
            const uint32_t akb = ((uint32_t)(ks * 32) + a_klane) ^ cswz;
            const uint32_t bkb = ((uint32_t)(ks * 32) + b_klane) ^ cswz;
            uint32_t ah[2][4], al[2][4];
            LDX4(ah[0], sA + a_rowoff + akb);
            LDX4(ah[1], sA + a_rowoff + 2048 + akb);
            if (two) {
                LDX4(al[0], sA2 + a_rowoff + akb);
                LDX4(al[1], sA2 + a_rowoff + 2048 + akb);
            }
            #pragma unroll
            for (int nb = 0; nb < 8; nb++) {
                uint32_t bb[4];
                LDX4(bb, sB + b_rowoff + nb * 2048 + bkb);
                #pragma unroll
                for (int ms = 0; ms < 2; ms++) {
                    MMA(acc[ms][2 * nb],     ah[ms], bb[0], bb[1]);
                    MMA(acc[ms][2 * nb + 1], ah[ms], bb[2], bb[3]);
                    if (two) {
                        MMA(acc[ms][2 * nb],     al[ms], bb[0], bb[1]);
                        MMA(acc[ms][2 * nb + 1], al[ms], bb[2], bb[3]);
                    }
                }
            }
        }
    }

    // ---- epilogue phase 1: acc + bias -> smem y (reuses stage memory) ------
    __syncthreads();           // all MMAs done before overwriting stages
    float* ys = (float*)(size_t)0;  // placeholder (unused)
    {
        // write via dynamic smem pointer arithmetic
    }
    float* ysm = reinterpret_cast<float*>(smraw + (base - smem_u32(smraw)));
    #pragma unroll
    for (int ms = 0; ms < 2; ms++) {
        const int r0 = wm * 32 + ms * 16 + (lane >> 2);
        const int r1 = r0 + 8;
        #pragma unroll
        for (int ns = 0; ns < 16; ns++) {
            const int c = wn * 128 + ns * 8 + (lane & 3) * 2;
            ysm[r0 * YS + c]     = acc[ms][ns][0] + sBias[c];
            ysm[r0 * YS + c + 1] = acc[ms][ns][1] + sBias[c + 1];
            ysm[r1 * YS + c]     = acc[ms][ns][2] + sBias[c];
            ysm[r1 * YS + c + 1] = acc[ms][ns][3] + sBias[c + 1];
        }
    }
    __syncthreads();

    // ---- epilogue phase 2: +residual, LN, exact GELU, final store ----------
    for (int r = wid; r < 64; r += 8) {
        const int gr = mtile * 64 + r;
        long toff = 0;
        if (res_trans | dst_trans) {
            int g = gr / N_, n = gr - g * N_;
            int bb2 = g / T_, tt = g - bb2 * T_;
            toff = ((long)(bb2 * N_ + n) * T_ + tt) * D_;
        }
        const float* rp = res + (res_trans ? toff : (long)gr * D_);
        float* dp = dst + (dst_trans ? toff : (long)gr * D_);
        const float* yp = ysm + r * YS;

        float v[16];
        float sum = 0.0f, sq = 0.0f;
        #pragma unroll
        for (int i = 0; i < 4; i++) {
            int c = lane * 4 + i * 128;
            float4 r4 = *(const float4*)(rp + c);
            float t0 = yp[c]     + r4.x;
            float t1 = yp[c + 1] + r4.y;
            float t2 = yp[c + 2] + r4.z;
            float t3 = yp[c + 3] + r4.w;
            v[i*4+0] = t0; v[i*4+1] = t1; v[i*4+2] = t2; v[i*4+3] = t3;
            sum += t0 + t1 + t2 + t3;
            sq = fmaf(t0, t0, sq); sq = fmaf(t1, t1, sq);
            sq = fmaf(t2, t2, sq); sq = fmaf(t3, t3, sq);
        }
        #pragma unroll
        for (int o = 16; o; o >>= 1) {
            sum += __shfl_xor_sync(0xffffffffu, sum, o);
            sq  += __shfl_xor_sync(0xffffffffu, sq, o);
        }
        float mu = sum * (1.0f / D_);
        float var = sq * (1.0f / D_) - mu * mu;
        float rstd = rsqrtf(var + LN_EPS);
        #pragma unroll
        for (int i = 0; i < 4; i++) {
            int c = lane * 4 + i * 128;
            float o0 = fmaf((v[i*4+0] - mu) * rstd, sGam[c],     sBet[c]);
            float o1 = fmaf((v[i*4+1] - mu) * rstd, sGam[c + 1], sBet[c + 1]);
            float o2 = fmaf((v[i*4+2] - mu) * rstd, sGam[c + 2], sBet[c + 2]);
            float o3 = fmaf((v[i*4+3] - mu) * rstd, sGam[c + 3], sBet[c + 3]);
            o0 = 0.5f * o0 * (1.0f + erff(o0 * 0.70710678118654752f));
            o1 = 0.5f * o1 * (1.0f + erff(o1 * 0.70710678118654752f));
            o2 = 0.5f * o2 * (1.0f + erff(o2 * 0.70710678118654752f));
            o3 = 0.5f * o3 * (1.0f + erff(o3 * 0.70710678118654752f));
            *(float4*)(dp + c) = make_float4(o0, o1, o2, o3);
        }
    }
}

// ---------------- launch -----------------------------------------------------
extern "C" void kernel_launch(void* const* d_in, const int* in_sizes, int n_in,
                              void* d_out, int out_size)
{
    const float* features  = (const float*)d_in[0];
    const float* adjacency = (const float*)d_in[1];
    const float* edge_w    = (const float*)d_in[2];
    const float* edge_b    = (const float*)d_in[3];
    const float* W         = (const float*)d_in[4];
    const float* bias      = (const float*)d_in[5];
    const float* gamma     = (const float*)d_in[6];
    const float* beta      = (const float*)d_in[7];
    float* out = (float*)d_out;

    unsigned char *ahi, *alo, *bhi, *blo;
    float *state;
    cudaGetSymbolAddress((void**)&ahi, g_ahi);
    cudaGetSymbolAddress((void**)&alo, g_alo);
    cudaGetSymbolAddress((void**)&bhi, g_bhi);
    cudaGetSymbolAddress((void**)&blo, g_blo);
    cudaGetSymbolAddress((void**)&state, g_state);

    cudaFuncSetAttribute(gemm_kernel, cudaFuncAttributeMaxDynamicSharedMemorySize,
                         GEMM_SMEM_DYN);

    adj_kernel<<<NGRAPH, 128>>>(adjacency, edge_w, edge_b);
    wconv_kernel<<<256, 256>>>(W);

    const size_t bl = (size_t)KCHUNKS * BTILE_BYTES;  // per-layer B block

    // layer 0: residual = features (transposed), dst = g_state (rows)
    mix_kernel<<<NGRAPH, 256>>>(features, 1);
    gemm_kernel<<<MTILES, 256, GEMM_SMEM_DYN>>>(ahi, alo, bhi, blo,
                                                features, 1, state, 0,
                                                gamma, beta, bias, 0);
    // layer 1: residual = g_state, dst = out (transposed)
    mix_kernel<<<NGRAPH, 256>>>(state, 0);
    gemm_kernel<<<MTILES, 256, GEMM_SMEM_DYN>>>(ahi, alo, bhi + bl, blo + bl,
                                                state, 0, out, 1,
                                                gamma, beta, bias, 1);
}

// round 7
// speedup vs baseline: 1.2407x; 1.2407x over previous
#include <cuda_runtime.h>
#include <cuda_bf16.h>
#include <math.h>
#include <stdint.h>

#define B_ 8
#define N_ 19
#define T_ 1000
#define D_ 512
#define ALPHA 0.05f
#define LN_EPS 1e-5f
#define ROW_EPS 1e-6f

#define NGRAPH (B_ * T_)       // 8000
#define NROWS (NGRAPH * N_)    // 152000
#define MTILES 1188            // ceil(152000/128)
#define NTILES 4               // 512/128
#define KCHUNKS 8              // 512/64
#define ATILE_BYTES 16384      // 128 rows x 64 k x bf16 (swizzled)
#define BTILE_BYTES 16384      // 128 n   x 64 k x bf16 (swizzled)
#define STAGE_BYTES 65536
#define NSTAGES 3
#define GEMM_SMEM_DYN (NSTAGES * STAGE_BYTES + 1024)

// ---------------- scratch (__device__ globals; no runtime alloc) ------------
__device__ __align__(16) unsigned char g_ahi[(size_t)MTILES * KCHUNKS * ATILE_BYTES];
__device__ __align__(16) unsigned char g_alo[(size_t)MTILES * KCHUNKS * ATILE_BYTES];
__device__ __align__(16) unsigned char g_bhi[2 * KCHUNKS * NTILES * BTILE_BYTES];
__device__ __align__(16) unsigned char g_blo[2 * KCHUNKS * NTILES * BTILE_BYTES];
__device__ float g_adjn[(size_t)NGRAPH * N_ * N_];
__device__ float g_state[(size_t)NROWS * D_];
__device__ float g_y[(size_t)MTILES * 128 * D_];

// ---------------- helpers ---------------------------------------------------
__device__ __forceinline__ uint32_t swz(uint32_t o) { return o ^ ((o >> 3) & 0x70); }

__device__ __forceinline__ uint32_t smem_u32(const void* p) {
    uint32_t a;
    asm("{ .reg .u64 t; cvta.to.shared.u64 t, %1; cvt.u32.u64 %0, t; }" : "=r"(a) : "l"(p));
    return a;
}
__device__ __forceinline__ void bulk_g2s(uint32_t dst, const void* src,
                                         uint32_t bytes, uint32_t mbar) {
    asm volatile(
        "cp.async.bulk.shared::cta.global.mbarrier::complete_tx::bytes [%0], [%1], %2, [%3];"
        :: "r"(dst), "l"(src), "r"(bytes), "r"(mbar) : "memory");
}
#define MBAR_INIT(a, c) asm volatile("mbarrier.init.shared.b64 [%0], %1;" :: "r"(a), "r"(c) : "memory")
#define MBAR_EXPECT(a, b) asm volatile("mbarrier.arrive.expect_tx.shared.b64 _, [%0], %1;" :: "r"(a), "r"(b) : "memory")
#define MBAR_WAIT(addr, ph) do {                                                      \
    asm volatile(                                                                     \
        "{\n\t.reg .pred P;\n\t"                                                      \
        "WL_%=:\n\t"                                                                  \
        "mbarrier.try_wait.parity.acquire.cta.shared::cta.b64 P, [%0], %1, 0x989680;\n\t" \
        "@P bra.uni WD_%=;\n\t"                                                       \
        "bra.uni WL_%=;\n\t"                                                          \
        "WD_%=:\n\t}"                                                                 \
        :: "r"(addr), "r"(ph) : "memory");                                            \
} while (0)

#define LDX4(r, a)                                                                    \
    asm volatile("ldmatrix.sync.aligned.m8n8.x4.shared.b16 {%0,%1,%2,%3}, [%4];"      \
        : "=r"((r)[0]), "=r"((r)[1]), "=r"((r)[2]), "=r"((r)[3]) : "r"(a))

#define MMA(c, a, b0v, b1v)                                                           \
    asm volatile("mma.sync.aligned.m16n8k16.row.col.f32.bf16.bf16.f32 "               \
        "{%0,%1,%2,%3},{%4,%5,%6,%7},{%8,%9},{%0,%1,%2,%3};"                          \
        : "+f"((c)[0]), "+f"((c)[1]), "+f"((c)[2]), "+f"((c)[3])                      \
        : "r"((a)[0]), "r"((a)[1]), "r"((a)[2]), "r"((a)[3]), "r"(b0v), "r"(b1v))

// ---------------- adjacency softplus + row-normalize ------------------------
__global__ __launch_bounds__(128)
void adj_kernel(const float* __restrict__ adjacency,
                const float* __restrict__ edge_w, const float* __restrict__ edge_b)
{
    __shared__ float s[N_][N_];
    int g = blockIdx.x, tid = threadIdx.x;
    float ew = edge_w[0], eb = edge_b[0];
    const float* a = adjacency + (size_t)g * N_ * N_;
    for (int i = tid; i < N_ * N_; i += 128) {
        float v = fmaf(a[i], ew, eb);
        ((float*)s)[i] = fmaxf(v, 0.0f) + log1pf(expf(-fabsf(v)));
    }
    __syncthreads();
    if (tid < N_) {
        float sum = 0.0f;
        #pragma unroll
        for (int j = 0; j < N_; j++) sum += s[tid][j];
        float inv = 1.0f / (sum + ROW_EPS);
        #pragma unroll
        for (int j = 0; j < N_; j++) s[tid][j] *= inv;
    }
    __syncthreads();
    for (int i = tid; i < N_ * N_; i += 128)
        g_adjn[(size_t)g * N_ * N_ + i] = ((float*)s)[i];
}

// ---------------- W -> bf16 hi/lo W^T tiles (n-major, swizzled) -------------
__global__ __launch_bounds__(256)
void wconv_kernel(const float* __restrict__ W)
{
    int p = blockIdx.x * 256 + threadIdx.x;
    if (p >= 2 * 512 * 64) return;
    int l = p >> 15;
    int rem = p & 32767;
    int n = rem >> 6;
    int k8 = rem & 63;
    int k0 = k8 * 8;
    const float* src = W + (size_t)l * D_ * D_ + n;
    union { uint4 q; __nv_bfloat16 h[8]; } H, L;
    #pragma unroll
    for (int i = 0; i < 8; i++) {
        float w = src[(size_t)(k0 + i) * D_];
        H.h[i] = __float2bfloat16(w);
        L.h[i] = __float2bfloat16(w - __bfloat162float(H.h[i]));
    }
    int kchunk = k0 >> 6, nq = n >> 7, nl = n & 127, kl = k0 & 63;
    size_t blk = (size_t)l * (KCHUNKS * NTILES) + kchunk * NTILES + nq;
    uint32_t off = swz((uint32_t)(nl * 128 + kl * 2));
    *(uint4*)(g_bhi + blk * BTILE_BYTES + off) = H.q;
    *(uint4*)(g_blo + blk * BTILE_BYTES + off) = L.q;
}

// ---------------- shared mixing routine (operates on xs in smem) ------------
__device__ __forceinline__ void do_mix_split(const float (*xs)[D_],
                                             const float (*sadj)[N_],
                                             int g, int tid)
{
    for (int task = tid; task < N_ * 64; task += 256) {
        int n = task >> 6, k8 = task & 63, d0 = k8 << 3;
        float m[8];
        #pragma unroll
        for (int i = 0; i < 8; i++) m[i] = (1.0f - ALPHA) * xs[n][d0 + i];
        #pragma unroll
        for (int j = 0; j < N_; j++) {
            float a = ALPHA * sadj[n][j];
            #pragma unroll
            for (int i = 0; i < 8; i++) m[i] = fmaf(a, xs[j][d0 + i], m[i]);
        }
        union { uint4 q; __nv_bfloat16 h[8]; } H, L;
        #pragma unroll
        for (int i = 0; i < 8; i++) {
            H.h[i] = __float2bfloat16(m[i]);
            L.h[i] = __float2bfloat16(m[i] - __bfloat162float(H.h[i]));
        }
        int r = g * N_ + n;
        int mt = r >> 7, rl = r & 127;
        size_t blk = (size_t)mt * KCHUNKS + (k8 >> 3);
        uint32_t off = swz((uint32_t)(rl * 128 + (k8 & 7) * 16));
        *(uint4*)(g_ahi + blk * ATILE_BYTES + off) = H.q;
        *(uint4*)(g_alo + blk * ATILE_BYTES + off) = L.q;
    }
}

// ---------------- layer-0 mix: features -> A tiles ---------------------------
__global__ __launch_bounds__(256)
void mix_kernel(const float* __restrict__ src)
{
    __shared__ float xs[N_][D_];
    __shared__ float sadj[N_][N_];
    int g = blockIdx.x, tid = threadIdx.x;
    for (int i = tid; i < N_ * N_; i += 256)
        ((float*)sadj)[i] = g_adjn[(size_t)g * N_ * N_ + i];
    int bb = g / T_, tt = g - bb * T_;
    long tb = (long)bb * N_ * T_ * D_ + (long)tt * D_;
    for (int idx = tid; idx < N_ * D_; idx += 256) {
        int n = idx >> 9, d = idx & (D_ - 1);
        xs[n][d] = src[tb + (long)n * T_ * D_ + d];
    }
    __syncthreads();
    do_mix_split(xs, sadj, g, tid);
}

// ---------------- fused: layer-0 LN/GELU + layer-1 mix ----------------------
// reads y (gemm0 out) + features residual; writes g_state AND layer-1 A tiles.
__global__ __launch_bounds__(256)
void lnmix_kernel(const float* __restrict__ y,
                  const float* __restrict__ features,
                  const float* __restrict__ gamma, const float* __restrict__ beta,
                  const float* __restrict__ bias)
{
    __shared__ float xs[N_][D_];
    __shared__ float sadj[N_][N_];
    int g = blockIdx.x, tid = threadIdx.x;
    int wid = tid >> 5, lane = tid & 31;
    for (int i = tid; i < N_ * N_; i += 256)
        ((float*)sadj)[i] = g_adjn[(size_t)g * N_ * N_ + i];

    int bb = g / T_, tt = g - bb * T_;
    const long tb = (long)bb * N_ * T_ * D_ + (long)tt * D_;

    // LN + GELU per row (8 warps cover 19 rows)
    for (int r = wid; r < N_; r += 8) {
        const long row = (long)g * N_ + r;
        const float* yp = y + row * D_;
        const float* rp = features + tb + (long)r * T_ * D_;
        float v[16];
        float sum = 0.0f, sq = 0.0f;
        #pragma unroll
        for (int i = 0; i < 4; i++) {
            int c = lane * 4 + i * 128;
            float4 a = *(const float4*)(yp + c);
            float4 r4 = *(const float4*)(rp + c);
            float4 b4 = *(const float4*)(bias + c);
            float t0 = a.x + b4.x + r4.x, t1 = a.y + b4.y + r4.y;
            float t2 = a.z + b4.z + r4.z, t3 = a.w + b4.w + r4.w;
            v[i*4+0] = t0; v[i*4+1] = t1; v[i*4+2] = t2; v[i*4+3] = t3;
            sum += t0 + t1 + t2 + t3;
            sq = fmaf(t0, t0, sq); sq = fmaf(t1, t1, sq);
            sq = fmaf(t2, t2, sq); sq = fmaf(t3, t3, sq);
        }
        #pragma unroll
        for (int o = 16; o; o >>= 1) {
            sum += __shfl_xor_sync(0xffffffffu, sum, o);
            sq  += __shfl_xor_sync(0xffffffffu, sq, o);
        }
        float mu = sum * (1.0f / D_);
        float var = sq * (1.0f / D_) - mu * mu;
        float rstd = rsqrtf(var + LN_EPS);
        float* sp = g_state + row * D_;
        #pragma unroll
        for (int i = 0; i < 4; i++) {
            int c = lane * 4 + i * 128;
            float4 g4 = *(const float4*)(gamma + c);
            float4 be4 = *(const float4*)(beta + c);
            float o0 = fmaf((v[i*4+0] - mu) * rstd, g4.x, be4.x);
            float o1 = fmaf((v[i*4+1] - mu) * rstd, g4.y, be4.y);
            float o2 = fmaf((v[i*4+2] - mu) * rstd, g4.z, be4.z);
            float o3 = fmaf((v[i*4+3] - mu) * rstd, g4.w, be4.w);
            o0 = 0.5f * o0 * (1.0f + erff(o0 * 0.70710678118654752f));
            o1 = 0.5f * o1 * (1.0f + erff(o1 * 0.70710678118654752f));
            o2 = 0.5f * o2 * (1.0f + erff(o2 * 0.70710678118654752f));
            o3 = 0.5f * o3 * (1.0f + erff(o3 * 0.70710678118654752f));
            xs[r][c] = o0; xs[r][c+1] = o1; xs[r][c+2] = o2; xs[r][c+3] = o3;
            *(float4*)(sp + c) = make_float4(o0, o1, o2, o3);
        }
    }
    __syncthreads();
    do_mix_split(xs, sadj, g, tid);
}

// ---------------- GEMM: 128x128 CTA tile, 3-stage pipeline -------------------
__global__ __launch_bounds__(256, 1)
void gemm_kernel(const unsigned char* __restrict__ gAh,
                 const unsigned char* __restrict__ gAl,
                 const unsigned char* __restrict__ gBh,
                 const unsigned char* __restrict__ gBl,
                 float* __restrict__ y)
{
    extern __shared__ unsigned char smraw[];
    __shared__ __align__(8) unsigned long long s_mbar[NSTAGES];

    const int tid = threadIdx.x, wid = tid >> 5, lane = tid & 31;
    const int wm = wid >> 1, wn = wid & 1;
    const int mtile = blockIdx.x >> 2, nt = blockIdx.x & 3;

    const uint32_t base = (smem_u32(smraw) + 1023) & ~1023u;
    uint32_t mb[NSTAGES];
    #pragma unroll
    for (int i = 0; i < NSTAGES; i++) mb[i] = smem_u32(&s_mbar[0]) + 8 * i;
    if (tid == 0)
        for (int i = 0; i < NSTAGES; i++) MBAR_INIT(mb[i], 1);
    __syncthreads();

    const unsigned char* pAh = gAh + (size_t)mtile * KCHUNKS * ATILE_BYTES;
    const unsigned char* pAl = gAl + (size_t)mtile * KCHUNKS * ATILE_BYTES;
    const unsigned char* pBh = gBh + (size_t)nt * BTILE_BYTES;
    const unsigned char* pBl = gBl + (size_t)nt * BTILE_BYTES;

    const uint32_t a_rowoff = (wm * 32 + (lane & 15)) * 128;
    const uint32_t a_klane = (uint32_t)(lane >> 4) << 4;
    const uint32_t b_rowoff = (wn * 64 + ((lane >> 4) << 3) + (lane & 7)) * 128;
    const uint32_t b_klane = (uint32_t)((lane >> 3) & 1) << 4;
    const uint32_t cswz = (uint32_t)(lane & 7) << 4;

    float acc[2][8][4];
    #pragma unroll
    for (int ms = 0; ms < 2; ms++)
        #pragma unroll
        for (int ns = 0; ns < 8; ns++)
            #pragma unroll
            for (int q = 0; q < 4; q++) acc[ms][ns][q] = 0.0f;

    // prologue: issue stages 0 and 1
    if (tid == 0) {
        #pragma unroll
        for (int s = 0; s < 2; s++) {
            const uint32_t st = base + s * STAGE_BYTES;
            MBAR_EXPECT(mb[s], (uint32_t)STAGE_BYTES);
            bulk_g2s(st,         pAh + (size_t)s * ATILE_BYTES, ATILE_BYTES, mb[s]);
            bulk_g2s(st + 16384, pAl + (size_t)s * ATILE_BYTES, ATILE_BYTES, mb[s]);
            bulk_g2s(st + 32768, pBh + (size_t)s * NTILES * BTILE_BYTES, BTILE_BYTES, mb[s]);
            bulk_g2s(st + 49152, pBl + (size_t)s * NTILES * BTILE_BYTES, BTILE_BYTES, mb[s]);
        }
    }

    for (int kc = 0; kc < KCHUNKS; kc++) {
        const int slot = kc % NSTAGES;
        MBAR_WAIT(mb[slot], (kc / NSTAGES) & 1);
        __syncthreads();   // all threads done with stage kc-1 (aliases kc+2's slot)
        if (tid == 0 && kc + 2 < KCHUNKS) {
            const int kn = kc + 2, sl = kn % NSTAGES;
            const uint32_t st = base + sl * STAGE_BYTES;
            MBAR_EXPECT(mb[sl], (uint32_t)STAGE_BYTES);
            bulk_g2s(st,         pAh + (size_t)kn * ATILE_BYTES, ATILE_BYTES, mb[sl]);
            bulk_g2s(st + 16384, pAl + (size_t)kn * ATILE_BYTES, ATILE_BYTES, mb[sl]);
            bulk_g2s(st + 32768, pBh + (size_t)kn * NTILES * BTILE_BYTES, BTILE_BYTES, mb[sl]);
            bulk_g2s(st + 49152, pBl + (size_t)kn * NTILES * BTILE_BYTES, BTILE_BYTES, mb[sl]);
        }
        const uint32_t st = base + slot * STAGE_BYTES;
        const uint32_t sAh = st, sAl = st + 16384, sBh = st + 32768, sBl = st + 49152;

        #pragma unroll
        for (int ks = 0; ks < 4; ks++) {
            const uint32_t akb = ((uint32_t)(ks * 32) + a_klane) ^ cswz;
            const uint32_t bkb = ((uint32_t)(ks * 32) + b_klane) ^ cswz;
            uint32_t ah[2][4], al[2][4];
            LDX4(ah[0], sAh + a_rowoff + akb);
            LDX4(ah[1], sAh + a_rowoff + 2048 + akb);
            LDX4(al[0], sAl + a_rowoff + akb);
            LDX4(al[1], sAl + a_rowoff + 2048 + akb);
            uint32_t bh[4][4], bl[4][4];
            #pragma unroll
            for (int nb = 0; nb < 4; nb++) {
                LDX4(bh[nb], sBh + b_rowoff + nb * 2048 + bkb);
                LDX4(bl[nb], sBl + b_rowoff + nb * 2048 + bkb);
            }
            #pragma unroll
            for (int ms = 0; ms < 2; ms++) {
                #pragma unroll
                for (int ns = 0; ns < 8; ns++) {
                    const uint32_t* BH = &bh[ns >> 1][(ns & 1) * 2];
                    const uint32_t* BL = &bl[ns >> 1][(ns & 1) * 2];
                    MMA(acc[ms][ns], ah[ms], BH[0], BH[1]);
                    MMA(acc[ms][ns], ah[ms], BL[0], BL[1]);
                    MMA(acc[ms][ns], al[ms], BH[0], BH[1]);
                }
            }
        }
    }

    const int mrow = mtile * 128 + wm * 32;
    const int ncol = nt * 128 + wn * 64;
    #pragma unroll
    for (int ms = 0; ms < 2; ms++) {
        const int r0 = mrow + ms * 16 + (lane >> 2);
        const int r1 = r0 + 8;
        #pragma unroll
        for (int ns = 0; ns < 8; ns++) {
            const int c = ncol + ns * 8 + (lane & 3) * 2;
            if (r0 < NROWS)
                *(float2*)(y + (size_t)r0 * D_ + c) = make_float2(acc[ms][ns][0], acc[ms][ns][1]);
            if (r1 < NROWS)
                *(float2*)(y + (size_t)r1 * D_ + c) = make_float2(acc[ms][ns][2], acc[ms][ns][3]);
        }
    }
}

// ---------------- final: bias + residual + LN + exact GELU -> out ------------
__global__ __launch_bounds__(256)
void ln_kernel(const float* __restrict__ y,
               const float* __restrict__ res,
               float* __restrict__ dst,
               const float* __restrict__ gamma, const float* __restrict__ beta,
               const float* __restrict__ bias)
{
    int row = blockIdx.x * 8 + (threadIdx.x >> 5);
    int lane = threadIdx.x & 31;
    if (row >= NROWS) return;
    int g = row / N_, n = row - g * N_;
    int bb = g / T_, tt = g - bb * T_;
    long toff = ((long)(bb * N_ + n) * T_ + tt) * D_;

    const float* rp = res + (long)row * D_;
    float* dp = dst + toff;
    const float* yp = y + (long)row * D_;

    float v[16];
    float sum = 0.0f, sq = 0.0f;
    #pragma unroll
    for (int i = 0; i < 4; i++) {
        int c = lane * 4 + i * 128;
        float4 a = *(const float4*)(yp + c);
        float4 r4 = *(const float4*)(rp + c);
        float4 b4 = *(const float4*)(bias + c);
        float t0 = a.x + b4.x + r4.x, t1 = a.y + b4.y + r4.y;
        float t2 = a.z + b4.z + r4.z, t3 = a.w + b4.w + r4.w;
        v[i*4+0] = t0; v[i*4+1] = t1; v[i*4+2] = t2; v[i*4+3] = t3;
        sum += t0 + t1 + t2 + t3;
        sq = fmaf(t0, t0, sq); sq = fmaf(t1, t1, sq);
        sq = fmaf(t2, t2, sq); sq = fmaf(t3, t3, sq);
    }
    #pragma unroll
    for (int o = 16; o; o >>= 1) {
        sum += __shfl_xor_sync(0xffffffffu, sum, o);
        sq  += __shfl_xor_sync(0xffffffffu, sq, o);
    }
    float mu = sum * (1.0f / D_);
    float var = sq * (1.0f / D_) - mu * mu;
    float rstd = rsqrtf(var + LN_EPS);
    #pragma unroll
    for (int i = 0; i < 4; i++) {
        int c = lane * 4 + i * 128;
        float4 g4 = *(const float4*)(gamma + c);
        float4 be4 = *(const float4*)(beta + c);
        float o0 = fmaf((v[i*4+0] - mu) * rstd, g4.x, be4.x);
        float o1 = fmaf((v[i*4+1] - mu) * rstd, g4.y, be4.y);
        float o2 = fmaf((v[i*4+2] - mu) * rstd, g4.z, be4.z);
        float o3 = fmaf((v[i*4+3] - mu) * rstd, g4.w, be4.w);
        o0 = 0.5f * o0 * (1.0f + erff(o0 * 0.70710678118654752f));
        o1 = 0.5f * o1 * (1.0f + erff(o1 * 0.70710678118654752f));
        o2 = 0.5f * o2 * (1.0f + erff(o2 * 0.70710678118654752f));
        o3 = 0.5f * o3 * (1.0f + erff(o3 * 0.70710678118654752f));
        *(float4*)(dp + c) = make_float4(o0, o1, o2, o3);
    }
}

// ---------------- launch -----------------------------------------------------
extern "C" void kernel_launch(void* const* d_in, const int* in_sizes, int n_in,
                              void* d_out, int out_size)
{
    const float* features  = (const float*)d_in[0];
    const float* adjacency = (const float*)d_in[1];
    const float* edge_w    = (const float*)d_in[2];
    const float* edge_b    = (const float*)d_in[3];
    const float* W         = (const float*)d_in[4];
    const float* bias      = (const float*)d_in[5];
    const float* gamma     = (const float*)d_in[6];
    const float* beta      = (const float*)d_in[7];
    float* out = (float*)d_out;

    unsigned char *ahi, *alo, *bhi, *blo;
    float *yv, *state;
    cudaGetSymbolAddress((void**)&ahi, g_ahi);
    cudaGetSymbolAddress((void**)&alo, g_alo);
    cudaGetSymbolAddress((void**)&bhi, g_bhi);
    cudaGetSymbolAddress((void**)&blo, g_blo);
    cudaGetSymbolAddress((void**)&yv, g_y);
    cudaGetSymbolAddress((void**)&state, g_state);

    cudaFuncSetAttribute(gemm_kernel, cudaFuncAttributeMaxDynamicSharedMemorySize,
                         GEMM_SMEM_DYN);

    adj_kernel<<<NGRAPH, 128>>>(adjacency, edge_w, edge_b);
    wconv_kernel<<<256, 256>>>(W);

    const size_t bl = (size_t)KCHUNKS * NTILES * BTILE_BYTES;

    // layer 0
    mix_kernel<<<NGRAPH, 256>>>(features);
    gemm_kernel<<<MTILES * NTILES, 256, GEMM_SMEM_DYN>>>(ahi, alo, bhi, blo, yv);
    // fused: layer-0 LN/GELU (writes state) + layer-1 mix (writes A tiles)
    lnmix_kernel<<<NGRAPH, 256>>>(yv, features, gamma, beta, bias);
    // layer 1
    gemm_kernel<<<MTILES * NTILES, 256, GEMM_SMEM_DYN>>>(ahi, alo, bhi + bl, blo + bl, yv);
    ln_kernel<<<(NROWS + 7) / 8, 256>>>(yv, state, out,
                                        gamma + D_, beta + D_, bias + D_);
}

// round 8
// speedup vs baseline: 1.4588x; 1.1758x over previous
#include <cuda_runtime.h>
#include <cuda_fp16.h>
#include <math.h>
#include <stdint.h>

#define B_ 8
#define N_ 19
#define T_ 1000
#define D_ 512
#define ALPHA 0.05f
#define LN_EPS 1e-5f
#define ROW_EPS 1e-6f

#define NGRAPH (B_ * T_)       // 8000
#define NROWS (NGRAPH * N_)    // 152000
#define MTILES 1188            // ceil(152000/128)
#define NTILES 4               // 512/128
#define KCHUNKS 8              // 512/64
#define ATILE_BYTES 16384      // 128 rows x 64 k x fp16 (swizzled)
#define BTILE_BYTES 16384      // 128 n   x 64 k x fp16 (swizzled)
#define STAGE_BYTES 49152      // A(16K) + Bhi(16K) + Blo(16K)
#define NSTAGES 4
#define GEMM_SMEM_DYN (NSTAGES * STAGE_BYTES + 1024)

// ---------------- scratch (__device__ globals; no runtime alloc) ------------
__device__ __align__(16) unsigned char g_a[(size_t)MTILES * KCHUNKS * ATILE_BYTES];
__device__ __align__(16) unsigned char g_bhi[2 * KCHUNKS * NTILES * BTILE_BYTES];
__device__ __align__(16) unsigned char g_blo[2 * KCHUNKS * NTILES * BTILE_BYTES];
__device__ float g_adjn[(size_t)NGRAPH * N_ * N_];
__device__ float g_state[(size_t)NROWS * D_];
__device__ float g_y[(size_t)MTILES * 128 * D_];

// ---------------- helpers ---------------------------------------------------
__device__ __forceinline__ uint32_t swz(uint32_t o) { return o ^ ((o >> 3) & 0x70); }

__device__ __forceinline__ uint32_t smem_u32(const void* p) {
    uint32_t a;
    asm("{ .reg .u64 t; cvta.to.shared.u64 t, %1; cvt.u32.u64 %0, t; }" : "=r"(a) : "l"(p));
    return a;
}
__device__ __forceinline__ void bulk_g2s(uint32_t dst, const void* src,
                                         uint32_t bytes, uint32_t mbar) {
    asm volatile(
        "cp.async.bulk.shared::cta.global.mbarrier::complete_tx::bytes [%0], [%1], %2, [%3];"
        :: "r"(dst), "l"(src), "r"(bytes), "r"(mbar) : "memory");
}
#define MBAR_INIT(a, c) asm volatile("mbarrier.init.shared.b64 [%0], %1;" :: "r"(a), "r"(c) : "memory")
#define MBAR_EXPECT(a, b) asm volatile("mbarrier.arrive.expect_tx.shared.b64 _, [%0], %1;" :: "r"(a), "r"(b) : "memory")
#define MBAR_WAIT(addr, ph) do {                                                      \
    asm volatile(                                                                     \
        "{\n\t.reg .pred P;\n\t"                                                      \
        "WL_%=:\n\t"                                                                  \
        "mbarrier.try_wait.parity.acquire.cta.shared::cta.b64 P, [%0], %1, 0x989680;\n\t" \
        "@P bra.uni WD_%=;\n\t"                                                       \
        "bra.uni WL_%=;\n\t"                                                          \
        "WD_%=:\n\t}"                                                                 \
        :: "r"(addr), "r"(ph) : "memory");                                            \
} while (0)

#define LDX4(r, a)                                                                    \
    asm volatile("ldmatrix.sync.aligned.m8n8.x4.shared.b16 {%0,%1,%2,%3}, [%4];"      \
        : "=r"((r)[0]), "=r"((r)[1]), "=r"((r)[2]), "=r"((r)[3]) : "r"(a))

#define MMA(c, a, b0v, b1v)                                                           \
    asm volatile("mma.sync.aligned.m16n8k16.row.col.f32.f16.f16.f32 "                 \
        "{%0,%1,%2,%3},{%4,%5,%6,%7},{%8,%9},{%0,%1,%2,%3};"                          \
        : "+f"((c)[0]), "+f"((c)[1]), "+f"((c)[2]), "+f"((c)[3])                      \
        : "r"((a)[0]), "r"((a)[1]), "r"((a)[2]), "r"((a)[3]), "r"(b0v), "r"(b1v))

// ---------------- adjacency softplus + row-normalize ------------------------
__global__ __launch_bounds__(128)
void adj_kernel(const float* __restrict__ adjacency,
                const float* __restrict__ edge_w, const float* __restrict__ edge_b)
{
    __shared__ float s[N_][N_];
    int g = blockIdx.x, tid = threadIdx.x;
    float ew = edge_w[0], eb = edge_b[0];
    const float* a = adjacency + (size_t)g * N_ * N_;
    for (int i = tid; i < N_ * N_; i += 128) {
        float v = fmaf(a[i], ew, eb);
        ((float*)s)[i] = fmaxf(v, 0.0f) + log1pf(expf(-fabsf(v)));
    }
    __syncthreads();
    if (tid < N_) {
        float sum = 0.0f;
        #pragma unroll
        for (int j = 0; j < N_; j++) sum += s[tid][j];
        float inv = 1.0f / (sum + ROW_EPS);
        #pragma unroll
        for (int j = 0; j < N_; j++) s[tid][j] *= inv;
    }
    __syncthreads();
    for (int i = tid; i < N_ * N_; i += 128)
        g_adjn[(size_t)g * N_ * N_ + i] = ((float*)s)[i];
}

// ---------------- W -> fp16 hi/lo W^T tiles (n-major, swizzled) -------------
__global__ __launch_bounds__(256)
void wconv_kernel(const float* __restrict__ W)
{
    int p = blockIdx.x * 256 + threadIdx.x;
    if (p >= 2 * 512 * 64) return;
    int l = p >> 15;
    int rem = p & 32767;
    int n = rem >> 6;
    int k8 = rem & 63;
    int k0 = k8 * 8;
    const float* src = W + (size_t)l * D_ * D_ + n;
    union { uint4 q; __half h[8]; } H, L;
    #pragma unroll
    for (int i = 0; i < 8; i++) {
        float w = src[(size_t)(k0 + i) * D_];
        H.h[i] = __float2half_rn(w);
        L.h[i] = __float2half_rn(w - __half2float(H.h[i]));
    }
    int kchunk = k0 >> 6, nq = n >> 7, nl = n & 127, kl = k0 & 63;
    size_t blk = (size_t)l * (KCHUNKS * NTILES) + kchunk * NTILES + nq;
    uint32_t off = swz((uint32_t)(nl * 128 + kl * 2));
    *(uint4*)(g_bhi + blk * BTILE_BYTES + off) = H.q;
    *(uint4*)(g_blo + blk * BTILE_BYTES + off) = L.q;
}

// ---------------- shared mixing routine (operates on xs in smem) ------------
__device__ __forceinline__ void do_mix_split(const float (*xs)[D_],
                                             const float (*sadj)[N_],
                                             int g, int tid)
{
    for (int task = tid; task < N_ * 64; task += 256) {
        int n = task >> 6, k8 = task & 63, d0 = k8 << 3;
        float m[8];
        #pragma unroll
        for (int i = 0; i < 8; i++) m[i] = (1.0f - ALPHA) * xs[n][d0 + i];
        #pragma unroll
        for (int j = 0; j < N_; j++) {
            float a = ALPHA * sadj[n][j];
            #pragma unroll
            for (int i = 0; i < 8; i++) m[i] = fmaf(a, xs[j][d0 + i], m[i]);
        }
        union { uint4 q; __half h[8]; } H;
        #pragma unroll
        for (int i = 0; i < 8; i++) H.h[i] = __float2half_rn(m[i]);
        int r = g * N_ + n;
        int mt = r >> 7, rl = r & 127;
        size_t blk = (size_t)mt * KCHUNKS + (k8 >> 3);
        uint32_t off = swz((uint32_t)(rl * 128 + (k8 & 7) * 16));
        *(uint4*)(g_a + blk * ATILE_BYTES + off) = H.q;
    }
}

// ---------------- layer-0 mix: features -> A tiles ---------------------------
__global__ __launch_bounds__(256)
void mix_kernel(const float* __restrict__ src)
{
    __shared__ float xs[N_][D_];
    __shared__ float sadj[N_][N_];
    int g = blockIdx.x, tid = threadIdx.x;
    for (int i = tid; i < N_ * N_; i += 256)
        ((float*)sadj)[i] = g_adjn[(size_t)g * N_ * N_ + i];
    int bb = g / T_, tt = g - bb * T_;
    long tb = (long)bb * N_ * T_ * D_ + (long)tt * D_;
    for (int idx = tid; idx < N_ * D_; idx += 256) {
        int n = idx >> 9, d = idx & (D_ - 1);
        xs[n][d] = src[tb + (long)n * T_ * D_ + d];
    }
    __syncthreads();
    do_mix_split(xs, sadj, g, tid);
}

// ---------------- fused: layer-0 LN/GELU + layer-1 mix ----------------------
__global__ __launch_bounds__(256)
void lnmix_kernel(const float* __restrict__ y,
                  const float* __restrict__ features,
                  const float* __restrict__ gamma, const float* __restrict__ beta,
                  const float* __restrict__ bias)
{
    __shared__ float xs[N_][D_];
    __shared__ float sadj[N_][N_];
    int g = blockIdx.x, tid = threadIdx.x;
    int wid = tid >> 5, lane = tid & 31;
    for (int i = tid; i < N_ * N_; i += 256)
        ((float*)sadj)[i] = g_adjn[(size_t)g * N_ * N_ + i];

    int bb = g / T_, tt = g - bb * T_;
    const long tb = (long)bb * N_ * T_ * D_ + (long)tt * D_;

    for (int r = wid; r < N_; r += 8) {
        const long row = (long)g * N_ + r;
        const float* yp = y + row * D_;
        const float* rp = features + tb + (long)r * T_ * D_;
        float v[16];
        float sum = 0.0f, sq = 0.0f;
        #pragma unroll
        for (int i = 0; i < 4; i++) {
            int c = lane * 4 + i * 128;
            float4 a = *(const float4*)(yp + c);
            float4 r4 = *(const float4*)(rp + c);
            float4 b4 = *(const float4*)(bias + c);
            float t0 = a.x + b4.x + r4.x, t1 = a.y + b4.y + r4.y;
            float t2 = a.z + b4.z + r4.z, t3 = a.w + b4.w + r4.w;
            v[i*4+0] = t0; v[i*4+1] = t1; v[i*4+2] = t2; v[i*4+3] = t3;
            sum += t0 + t1 + t2 + t3;
            sq = fmaf(t0, t0, sq); sq = fmaf(t1, t1, sq);
            sq = fmaf(t2, t2, sq); sq = fmaf(t3, t3, sq);
        }
        #pragma unroll
        for (int o = 16; o; o >>= 1) {
            sum += __shfl_xor_sync(0xffffffffu, sum, o);
            sq  += __shfl_xor_sync(0xffffffffu, sq, o);
        }
        float mu = sum * (1.0f / D_);
        float var = sq * (1.0f / D_) - mu * mu;
        float rstd = rsqrtf(var + LN_EPS);
        float* sp = g_state + row * D_;
        #pragma unroll
        for (int i = 0; i < 4; i++) {
            int c = lane * 4 + i * 128;
            float4 g4 = *(const float4*)(gamma + c);
            float4 be4 = *(const float4*)(beta + c);
            float o0 = fmaf((v[i*4+0] - mu) * rstd, g4.x, be4.x);
            float o1 = fmaf((v[i*4+1] - mu) * rstd, g4.y, be4.y);
            float o2 = fmaf((v[i*4+2] - mu) * rstd, g4.z, be4.z);
            float o3 = fmaf((v[i*4+3] - mu) * rstd, g4.w, be4.w);
            o0 = 0.5f * o0 * (1.0f + erff(o0 * 0.70710678118654752f));
            o1 = 0.5f * o1 * (1.0f + erff(o1 * 0.70710678118654752f));
            o2 = 0.5f * o2 * (1.0f + erff(o2 * 0.70710678118654752f));
            o3 = 0.5f * o3 * (1.0f + erff(o3 * 0.70710678118654752f));
            xs[r][c] = o0; xs[r][c+1] = o1; xs[r][c+2] = o2; xs[r][c+3] = o3;
            *(float4*)(sp + c) = make_float4(o0, o1, o2, o3);
        }
    }
    __syncthreads();
    do_mix_split(xs, sadj, g, tid);
}

// ---------------- GEMM: 128x128 CTA tile, 2-term fp16 split, 4 stages -------
__global__ __launch_bounds__(256, 1)
void gemm_kernel(const unsigned char* __restrict__ gA,
                 const unsigned char* __restrict__ gBh,
                 const unsigned char* __restrict__ gBl,
                 float* __restrict__ y)
{
    extern __shared__ unsigned char smraw[];
    __shared__ __align__(8) unsigned long long s_mbar[NSTAGES];

    const int tid = threadIdx.x, wid = tid >> 5, lane = tid & 31;
    const int wm = wid >> 1, wn = wid & 1;
    const int mtile = blockIdx.x >> 2, nt = blockIdx.x & 3;

    const uint32_t base = (smem_u32(smraw) + 1023) & ~1023u;
    uint32_t mb[NSTAGES];
    #pragma unroll
    for (int i = 0; i < NSTAGES; i++) mb[i] = smem_u32(&s_mbar[0]) + 8 * i;
    if (tid == 0)
        for (int i = 0; i < NSTAGES; i++) MBAR_INIT(mb[i], 1);
    __syncthreads();

    const unsigned char* pA = gA + (size_t)mtile * KCHUNKS * ATILE_BYTES;
    const unsigned char* pBh = gBh + (size_t)nt * BTILE_BYTES;
    const unsigned char* pBl = gBl + (size_t)nt * BTILE_BYTES;

    const uint32_t a_rowoff = (wm * 32 + (lane & 15)) * 128;
    const uint32_t a_klane = (uint32_t)(lane >> 4) << 4;
    const uint32_t b_rowoff = (wn * 64 + ((lane >> 4) << 3) + (lane & 7)) * 128;
    const uint32_t b_klane = (uint32_t)((lane >> 3) & 1) << 4;
    const uint32_t cswz = (uint32_t)(lane & 7) << 4;

    float acc[2][8][4];
    #pragma unroll
    for (int ms = 0; ms < 2; ms++)
        #pragma unroll
        for (int ns = 0; ns < 8; ns++)
            #pragma unroll
            for (int q = 0; q < 4; q++) acc[ms][ns][q] = 0.0f;

    // prologue: issue stages 0..2
    if (tid == 0) {
        #pragma unroll
        for (int s = 0; s < 3; s++) {
            const uint32_t st = base + s * STAGE_BYTES;
            MBAR_EXPECT(mb[s], (uint32_t)STAGE_BYTES);
            bulk_g2s(st,         pA + (size_t)s * ATILE_BYTES, ATILE_BYTES, mb[s]);
            bulk_g2s(st + 16384, pBh + (size_t)s * NTILES * BTILE_BYTES, BTILE_BYTES, mb[s]);
            bulk_g2s(st + 32768, pBl + (size_t)s * NTILES * BTILE_BYTES, BTILE_BYTES, mb[s]);
        }
    }

    for (int kc = 0; kc < KCHUNKS; kc++) {
        const int slot = kc % NSTAGES;
        MBAR_WAIT(mb[slot], (kc / NSTAGES) & 1);
        __syncthreads();   // all threads done with stage kc-1 (slot reused by kc+3)
        if (tid == 0 && kc + 3 < KCHUNKS) {
            const int kn = kc + 3, sl = kn % NSTAGES;
            const uint32_t st = base + sl * STAGE_BYTES;
            MBAR_EXPECT(mb[sl], (uint32_t)STAGE_BYTES);
            bulk_g2s(st,         pA + (size_t)kn * ATILE_BYTES, ATILE_BYTES, mb[sl]);
            bulk_g2s(st + 16384, pBh + (size_t)kn * NTILES * BTILE_BYTES, BTILE_BYTES, mb[sl]);
            bulk_g2s(st + 32768, pBl + (size_t)kn * NTILES * BTILE_BYTES, BTILE_BYTES, mb[sl]);
        }
        const uint32_t st = base + slot * STAGE_BYTES;
        const uint32_t sA = st, sBh = st + 16384, sBl = st + 32768;

        #pragma unroll
        for (int ks = 0; ks < 4; ks++) {
            const uint32_t akb = ((uint32_t)(ks * 32) + a_klane) ^ cswz;
            const uint32_t bkb = ((uint32_t)(ks * 32) + b_klane) ^ cswz;
            uint32_t av[2][4];
            LDX4(av[0], sA + a_rowoff + akb);
            LDX4(av[1], sA + a_rowoff + 2048 + akb);
            uint32_t bh[4][4], bl[4][4];
            #pragma unroll
            for (int nb = 0; nb < 4; nb++) {
                LDX4(bh[nb], sBh + b_rowoff + nb * 2048 + bkb);
                LDX4(bl[nb], sBl + b_rowoff + nb * 2048 + bkb);
            }
            #pragma unroll
            for (int ms = 0; ms < 2; ms++) {
                #pragma unroll
                for (int ns = 0; ns < 8; ns++) {
                    const uint32_t* BH = &bh[ns >> 1][(ns & 1) * 2];
                    const uint32_t* BL = &bl[ns >> 1][(ns & 1) * 2];
                    MMA(acc[ms][ns], av[ms], BH[0], BH[1]);
                    MMA(acc[ms][ns], av[ms], BL[0], BL[1]);
                }
            }
        }
    }

    const int mrow = mtile * 128 + wm * 32;
    const int ncol = nt * 128 + wn * 64;
    #pragma unroll
    for (int ms = 0; ms < 2; ms++) {
        const int r0 = mrow + ms * 16 + (lane >> 2);
        const int r1 = r0 + 8;
        #pragma unroll
        for (int ns = 0; ns < 8; ns++) {
            const int c = ncol + ns * 8 + (lane & 3) * 2;
            if (r0 < NROWS)
                *(float2*)(y + (size_t)r0 * D_ + c) = make_float2(acc[ms][ns][0], acc[ms][ns][1]);
            if (r1 < NROWS)
                *(float2*)(y + (size_t)r1 * D_ + c) = make_float2(acc[ms][ns][2], acc[ms][ns][3]);
        }
    }
}

// ---------------- final: bias + residual + LN + exact GELU -> out ------------
__global__ __launch_bounds__(256)
void ln_kernel(const float* __restrict__ y,
               const float* __restrict__ res,
               float* __restrict__ dst,
               const float* __restrict__ gamma, const float* __restrict__ beta,
               const float* __restrict__ bias)
{
    int row = blockIdx.x * 8 + (threadIdx.x >> 5);
    int lane = threadIdx.x & 31;
    if (row >= NROWS) return;
    int g = row / N_, n = row - g * N_;
    int bb = g / T_, tt = g - bb * T_;
    long toff = ((long)(bb * N_ + n) * T_ + tt) * D_;

    const float* rp = res + (long)row * D_;
    float* dp = dst + toff;
    const float* yp = y + (long)row * D_;

    float v[16];
    float sum = 0.0f, sq = 0.0f;
    #pragma unroll
    for (int i = 0; i < 4; i++) {
        int c = lane * 4 + i * 128;
        float4 a = *(const float4*)(yp + c);
        float4 r4 = *(const float4*)(rp + c);
        float4 b4 = *(const float4*)(bias + c);
        float t0 = a.x + b4.x + r4.x, t1 = a.y + b4.y + r4.y;
        float t2 = a.z + b4.z + r4.z, t3 = a.w + b4.w + r4.w;
        v[i*4+0] = t0; v[i*4+1] = t1; v[i*4+2] = t2; v[i*4+3] = t3;
        sum += t0 + t1 + t2 + t3;
        sq = fmaf(t0, t0, sq); sq = fmaf(t1, t1, sq);
        sq = fmaf(t2, t2, sq); sq = fmaf(t3, t3, sq);
    }
    #pragma unroll
    for (int o = 16; o; o >>= 1) {
        sum += __shfl_xor_sync(0xffffffffu, sum, o);
        sq  += __shfl_xor_sync(0xffffffffu, sq, o);
    }
    float mu = sum * (1.0f / D_);
    float var = sq * (1.0f / D_) - mu * mu;
    float rstd = rsqrtf(var + LN_EPS);
    #pragma unroll
    for (int i = 0; i < 4; i++) {
        int c = lane * 4 + i * 128;
        float4 g4 = *(const float4*)(gamma + c);
        float4 be4 = *(const float4*)(beta + c);
        float o0 = fmaf((v[i*4+0] - mu) * rstd, g4.x, be4.x);
        float o1 = fmaf((v[i*4+1] - mu) * rstd, g4.y, be4.y);
        float o2 = fmaf((v[i*4+2] - mu) * rstd, g4.z, be4.z);
        float o3 = fmaf((v[i*4+3] - mu) * rstd, g4.w, be4.w);
        o0 = 0.5f * o0 * (1.0f + erff(o0 * 0.70710678118654752f));
        o1 = 0.5f * o1 * (1.0f + erff(o1 * 0.70710678118654752f));
        o2 = 0.5f * o2 * (1.0f + erff(o2 * 0.70710678118654752f));
        o3 = 0.5f * o3 * (1.0f + erff(o3 * 0.70710678118654752f));
        *(float4*)(dp + c) = make_float4(o0, o1, o2, o3);
    }
}

// ---------------- launch -----------------------------------------------------
extern "C" void kernel_launch(void* const* d_in, const int* in_sizes, int n_in,
                              void* d_out, int out_size)
{
    const float* features  = (const float*)d_in[0];
    const float* adjacency = (const float*)d_in[1];
    const float* edge_w    = (const float*)d_in[2];
    const float* edge_b    = (const float*)d_in[3];
    const float* W         = (const float*)d_in[4];
    const float* bias      = (const float*)d_in[5];
    const float* gamma     = (const float*)d_in[6];
    const float* beta      = (const float*)d_in[7];
    float* out = (float*)d_out;

    unsigned char *av, *bhi, *blo;
    float *yv, *state;
    cudaGetSymbolAddress((void**)&av, g_a);
    cudaGetSymbolAddress((void**)&bhi, g_bhi);
    cudaGetSymbolAddress((void**)&blo, g_blo);
    cudaGetSymbolAddress((void**)&yv, g_y);
    cudaGetSymbolAddress((void**)&state, g_state);

    cudaFuncSetAttribute(gemm_kernel, cudaFuncAttributeMaxDynamicSharedMemorySize,
                         GEMM_SMEM_DYN);

    adj_kernel<<<NGRAPH, 128>>>(adjacency, edge_w, edge_b);
    wconv_kernel<<<256, 256>>>(W);

    const size_t bl = (size_t)KCHUNKS * NTILES * BTILE_BYTES;

    // layer 0
    mix_kernel<<<NGRAPH, 256>>>(features);
    gemm_kernel<<<MTILES * NTILES, 256, GEMM_SMEM_DYN>>>(av, bhi, blo, yv);
    // fused: layer-0 LN/GELU (writes state) + layer-1 mix (writes A tiles)
    lnmix_kernel<<<NGRAPH, 256>>>(yv, features, gamma, beta, bias);
    // layer 1
    gemm_kernel<<<MTILES * NTILES, 256, GEMM_SMEM_DYN>>>(av, bhi + bl, blo + bl, yv);
    ln_kernel<<<(NROWS + 7) / 8, 256>>>(yv, state, out,
                                        gamma + D_, beta + D_, bias + D_);
}

// round 9
// speedup vs baseline: 1.8219x; 1.2489x over previous
#include <cuda_runtime.h>
#include <cuda_fp16.h>
#include <math.h>
#include <stdint.h>

#define B_ 8
#define N_ 19
#define T_ 1000
#define D_ 512
#define ALPHA 0.05f
#define LN_EPS 1e-5f
#define ROW_EPS 1e-6f

#define NGRAPH (B_ * T_)       // 8000
#define NROWS (NGRAPH * N_)    // 152000
#define MTILES 1188            // ceil(152000/128)
#define NTILES 4               // 512/128
#define KCHUNKS 8              // 512/64
#define ATILE_BYTES 16384      // 128 rows x 64 k x fp16 (swizzled)
#define BTILE_BYTES 16384      // 128 n   x 64 k x fp16 (swizzled)
#define STAGE_BYTES 32768      // A(16K) + B(16K)
#define NSTAGES 3
#define GEMM_SMEM_DYN (NSTAGES * STAGE_BYTES + 1024)

// ---------------- scratch (__device__ globals; no runtime alloc) ------------
__device__ __align__(16) unsigned char g_a[(size_t)MTILES * KCHUNKS * ATILE_BYTES];
__device__ __align__(16) unsigned char g_b[2 * KCHUNKS * NTILES * BTILE_BYTES];
__device__ float g_adjn[(size_t)NGRAPH * N_ * N_];
__device__ float g_state[(size_t)NROWS * D_];
__device__ float g_y[(size_t)MTILES * 128 * D_];

// ---------------- helpers ---------------------------------------------------
__device__ __forceinline__ uint32_t swz(uint32_t o) { return o ^ ((o >> 3) & 0x70); }

__device__ __forceinline__ uint32_t smem_u32(const void* p) {
    uint32_t a;
    asm("{ .reg .u64 t; cvta.to.shared.u64 t, %1; cvt.u32.u64 %0, t; }" : "=r"(a) : "l"(p));
    return a;
}
__device__ __forceinline__ void bulk_g2s(uint32_t dst, const void* src,
                                         uint32_t bytes, uint32_t mbar) {
    asm volatile(
        "cp.async.bulk.shared::cta.global.mbarrier::complete_tx::bytes [%0], [%1], %2, [%3];"
        :: "r"(dst), "l"(src), "r"(bytes), "r"(mbar) : "memory");
}
#define MBAR_INIT(a, c) asm volatile("mbarrier.init.shared.b64 [%0], %1;" :: "r"(a), "r"(c) : "memory")
#define MBAR_EXPECT(a, b) asm volatile("mbarrier.arrive.expect_tx.shared.b64 _, [%0], %1;" :: "r"(a), "r"(b) : "memory")
#define MBAR_WAIT(addr, ph) do {                                                      \
    asm volatile(                                                                     \
        "{\n\t.reg .pred P;\n\t"                                                      \
        "WL_%=:\n\t"                                                                  \
        "mbarrier.try_wait.parity.acquire.cta.shared::cta.b64 P, [%0], %1, 0x989680;\n\t" \
        "@P bra.uni WD_%=;\n\t"                                                       \
        "bra.uni WL_%=;\n\t"                                                          \
        "WD_%=:\n\t}"                                                                 \
        :: "r"(addr), "r"(ph) : "memory");                                            \
} while (0)

#define LDX4(r, a)                                                                    \
    asm volatile("ldmatrix.sync.aligned.m8n8.x4.shared.b16 {%0,%1,%2,%3}, [%4];"      \
        : "=r"((r)[0]), "=r"((r)[1]), "=r"((r)[2]), "=r"((r)[3]) : "r"(a))

#define MMA(c, a, b0v, b1v)                                                           \
    asm volatile("mma.sync.aligned.m16n8k16.row.col.f32.f16.f16.f32 "                 \
        "{%0,%1,%2,%3},{%4,%5,%6,%7},{%8,%9},{%0,%1,%2,%3};"                          \
        : "+f"((c)[0]), "+f"((c)[1]), "+f"((c)[2]), "+f"((c)[3])                      \
        : "r"((a)[0]), "r"((a)[1]), "r"((a)[2]), "r"((a)[3]), "r"(b0v), "r"(b1v))

// ---------------- adjacency softplus + row-normalize ------------------------
__global__ __launch_bounds__(128)
void adj_kernel(const float* __restrict__ adjacency,
                const float* __restrict__ edge_w, const float* __restrict__ edge_b)
{
    __shared__ float s[N_][N_];
    int g = blockIdx.x, tid = threadIdx.x;
    float ew = edge_w[0], eb = edge_b[0];
    const float* a = adjacency + (size_t)g * N_ * N_;
    for (int i = tid; i < N_ * N_; i += 128) {
        float v = fmaf(a[i], ew, eb);
        ((float*)s)[i] = fmaxf(v, 0.0f) + log1pf(expf(-fabsf(v)));
    }
    __syncthreads();
    if (tid < N_) {
        float sum = 0.0f;
        #pragma unroll
        for (int j = 0; j < N_; j++) sum += s[tid][j];
        float inv = 1.0f / (sum + ROW_EPS);
        #pragma unroll
        for (int j = 0; j < N_; j++) s[tid][j] *= inv;
    }
    __syncthreads();
    for (int i = tid; i < N_ * N_; i += 128)
        g_adjn[(size_t)g * N_ * N_ + i] = ((float*)s)[i];
}

// ---------------- W -> fp16 W^T tiles (n-major, swizzled) -------------------
__global__ __launch_bounds__(256)
void wconv_kernel(const float* __restrict__ W)
{
    int p = blockIdx.x * 256 + threadIdx.x;
    if (p >= 2 * 512 * 64) return;
    int l = p >> 15;
    int rem = p & 32767;
    int n = rem >> 6;
    int k8 = rem & 63;
    int k0 = k8 * 8;
    const float* src = W + (size_t)l * D_ * D_ + n;
    union { uint4 q; __half h[8]; } H;
    #pragma unroll
    for (int i = 0; i < 8; i++)
        H.h[i] = __float2half_rn(src[(size_t)(k0 + i) * D_]);
    int kchunk = k0 >> 6, nq = n >> 7, nl = n & 127, kl = k0 & 63;
    size_t blk = (size_t)l * (KCHUNKS * NTILES) + kchunk * NTILES + nq;
    uint32_t off = swz((uint32_t)(nl * 128 + kl * 2));
    *(uint4*)(g_b + blk * BTILE_BYTES + off) = H.q;
}

// ---------------- shared mixing routine (operates on xs in smem) ------------
__device__ __forceinline__ void do_mix_split(const float (*xs)[D_],
                                             const float (*sadj)[N_],
                                             int g, int tid)
{
    for (int task = tid; task < N_ * 64; task += 256) {
        int n = task >> 6, k8 = task & 63, d0 = k8 << 3;
        float m[8];
        #pragma unroll
        for (int i = 0; i < 8; i++) m[i] = (1.0f - ALPHA) * xs[n][d0 + i];
        #pragma unroll
        for (int j = 0; j < N_; j++) {
            float a = ALPHA * sadj[n][j];
            #pragma unroll
            for (int i = 0; i < 8; i++) m[i] = fmaf(a, xs[j][d0 + i], m[i]);
        }
        union { uint4 q; __half h[8]; } H;
        #pragma unroll
        for (int i = 0; i < 8; i++) H.h[i] = __float2half_rn(m[i]);
        int r = g * N_ + n;
        int mt = r >> 7, rl = r & 127;
        size_t blk = (size_t)mt * KCHUNKS + (k8 >> 3);
        uint32_t off = swz((uint32_t)(rl * 128 + (k8 & 7) * 16));
        *(uint4*)(g_a + blk * ATILE_BYTES + off) = H.q;
    }
}

// ---------------- layer-0 mix: features -> A tiles ---------------------------
__global__ __launch_bounds__(256)
void mix_kernel(const float* __restrict__ src)
{
    __shared__ float xs[N_][D_];
    __shared__ float sadj[N_][N_];
    int g = blockIdx.x, tid = threadIdx.x;
    for (int i = tid; i < N_ * N_; i += 256)
        ((float*)sadj)[i] = g_adjn[(size_t)g * N_ * N_ + i];
    int bb = g / T_, tt = g - bb * T_;
    long tb = (long)bb * N_ * T_ * D_ + (long)tt * D_;
    for (int idx = tid; idx < N_ * D_; idx += 256) {
        int n = idx >> 9, d = idx & (D_ - 1);
        xs[n][d] = src[tb + (long)n * T_ * D_ + d];
    }
    __syncthreads();
    do_mix_split(xs, sadj, g, tid);
}

// ---------------- fused: layer-0 LN/GELU + layer-1 mix ----------------------
__global__ __launch_bounds__(256)
void lnmix_kernel(const float* __restrict__ y,
                  const float* __restrict__ features,
                  const float* __restrict__ gamma, const float* __restrict__ beta,
                  const float* __restrict__ bias)
{
    __shared__ float xs[N_][D_];
    __shared__ float sadj[N_][N_];
    int g = blockIdx.x, tid = threadIdx.x;
    int wid = tid >> 5, lane = tid & 31;
    for (int i = tid; i < N_ * N_; i += 256)
        ((float*)sadj)[i] = g_adjn[(size_t)g * N_ * N_ + i];

    int bb = g / T_, tt = g - bb * T_;
    const long tb = (long)bb * N_ * T_ * D_ + (long)tt * D_;

    for (int r = wid; r < N_; r += 8) {
        const long row = (long)g * N_ + r;
        const float* yp = y + row * D_;
        const float* rp = features + tb + (long)r * T_ * D_;
        float v[16];
        float sum = 0.0f, sq = 0.0f;
        #pragma unroll
        for (int i = 0; i < 4; i++) {
            int c = lane * 4 + i * 128;
            float4 a = *(const float4*)(yp + c);
            float4 r4 = *(const float4*)(rp + c);
            float4 b4 = *(const float4*)(bias + c);
            float t0 = a.x + b4.x + r4.x, t1 = a.y + b4.y + r4.y;
            float t2 = a.z + b4.z + r4.z, t3 = a.w + b4.w + r4.w;
            v[i*4+0] = t0; v[i*4+1] = t1; v[i*4+2] = t2; v[i*4+3] = t3;
            sum += t0 + t1 + t2 + t3;
            sq = fmaf(t0, t0, sq); sq = fmaf(t1, t1, sq);
            sq = fmaf(t2, t2, sq); sq = fmaf(t3, t3, sq);
        }
        #pragma unroll
        for (int o = 16; o; o >>= 1) {
            sum += __shfl_xor_sync(0xffffffffu, sum, o);
            sq  += __shfl_xor_sync(0xffffffffu, sq, o);
        }
        float mu = sum * (1.0f / D_);
        float var = sq * (1.0f / D_) - mu * mu;
        float rstd = rsqrtf(var + LN_EPS);
        float* sp = g_state + row * D_;
        #pragma unroll
        for (int i = 0; i < 4; i++) {
            int c = lane * 4 + i * 128;
            float4 g4 = *(const float4*)(gamma + c);
            float4 be4 = *(const float4*)(beta + c);
            float o0 = fmaf((v[i*4+0] - mu) * rstd, g4.x, be4.x);
            float o1 = fmaf((v[i*4+1] - mu) * rstd, g4.y, be4.y);
            float o2 = fmaf((v[i*4+2] - mu) * rstd, g4.z, be4.z);
            float o3 = fmaf((v[i*4+3] - mu) * rstd, g4.w, be4.w);
            o0 = 0.5f * o0 * (1.0f + erff(o0 * 0.70710678118654752f));
            o1 = 0.5f * o1 * (1.0f + erff(o1 * 0.70710678118654752f));
            o2 = 0.5f * o2 * (1.0f + erff(o2 * 0.70710678118654752f));
            o3 = 0.5f * o3 * (1.0f + erff(o3 * 0.70710678118654752f));
            xs[r][c] = o0; xs[r][c+1] = o1; xs[r][c+2] = o2; xs[r][c+3] = o3;
            *(float4*)(sp + c) = make_float4(o0, o1, o2, o3);
        }
    }
    __syncthreads();
    do_mix_split(xs, sadj, g, tid);
}

// ---------------- GEMM: 128x128 CTA tile, single fp16 term, 2 CTA/SM --------
__global__ __launch_bounds__(256, 2)
void gemm_kernel(const unsigned char* __restrict__ gA,
                 const unsigned char* __restrict__ gB,
                 float* __restrict__ y)
{
    extern __shared__ unsigned char smraw[];
    __shared__ __align__(8) unsigned long long s_mbar[NSTAGES];

    const int tid = threadIdx.x, wid = tid >> 5, lane = tid & 31;
    const int wm = wid >> 1, wn = wid & 1;
    const int mtile = blockIdx.x >> 2, nt = blockIdx.x & 3;

    const uint32_t base = (smem_u32(smraw) + 1023) & ~1023u;
    uint32_t mb[NSTAGES];
    #pragma unroll
    for (int i = 0; i < NSTAGES; i++) mb[i] = smem_u32(&s_mbar[0]) + 8 * i;
    if (tid == 0)
        for (int i = 0; i < NSTAGES; i++) MBAR_INIT(mb[i], 1);
    __syncthreads();

    const unsigned char* pA = gA + (size_t)mtile * KCHUNKS * ATILE_BYTES;
    const unsigned char* pB = gB + (size_t)nt * BTILE_BYTES;

    const uint32_t a_rowoff = (wm * 32 + (lane & 15)) * 128;
    const uint32_t a_klane = (uint32_t)(lane >> 4) << 4;
    const uint32_t b_rowoff = (wn * 64 + ((lane >> 4) << 3) + (lane & 7)) * 128;
    const uint32_t b_klane = (uint32_t)((lane >> 3) & 1) << 4;
    const uint32_t cswz = (uint32_t)(lane & 7) << 4;

    float acc[2][8][4];
    #pragma unroll
    for (int ms = 0; ms < 2; ms++)
        #pragma unroll
        for (int ns = 0; ns < 8; ns++)
            #pragma unroll
            for (int q = 0; q < 4; q++) acc[ms][ns][q] = 0.0f;

    // prologue: issue stages 0 and 1
    if (tid == 0) {
        #pragma unroll
        for (int s = 0; s < 2; s++) {
            const uint32_t st = base + s * STAGE_BYTES;
            MBAR_EXPECT(mb[s], (uint32_t)STAGE_BYTES);
            bulk_g2s(st,         pA + (size_t)s * ATILE_BYTES, ATILE_BYTES, mb[s]);
            bulk_g2s(st + 16384, pB + (size_t)s * NTILES * BTILE_BYTES, BTILE_BYTES, mb[s]);
        }
    }

    for (int kc = 0; kc < KCHUNKS; kc++) {
        const int slot = kc % NSTAGES;
        MBAR_WAIT(mb[slot], (kc / NSTAGES) & 1);
        __syncthreads();   // all threads done with stage kc-1 (slot reused by kc+2)
        if (tid == 0 && kc + 2 < KCHUNKS) {
            const int kn = kc + 2, sl = kn % NSTAGES;
            const uint32_t st = base + sl * STAGE_BYTES;
            MBAR_EXPECT(mb[sl], (uint32_t)STAGE_BYTES);
            bulk_g2s(st,         pA + (size_t)kn * ATILE_BYTES, ATILE_BYTES, mb[sl]);
            bulk_g2s(st + 16384, pB + (size_t)kn * NTILES * BTILE_BYTES, BTILE_BYTES, mb[sl]);
        }
        const uint32_t st = base + slot * STAGE_BYTES;
        const uint32_t sA = st, sB = st + 16384;

        #pragma unroll
        for (int ks = 0; ks < 4; ks++) {
            const uint32_t akb = ((uint32_t)(ks * 32) + a_klane) ^ cswz;
            const uint32_t bkb = ((uint32_t)(ks * 32) + b_klane) ^ cswz;
            uint32_t av[2][4];
            LDX4(av[0], sA + a_rowoff + akb);
            LDX4(av[1], sA + a_rowoff + 2048 + akb);
            uint32_t bv[4][4];
            #pragma unroll
            for (int nb = 0; nb < 4; nb++)
                LDX4(bv[nb], sB + b_rowoff + nb * 2048 + bkb);
            #pragma unroll
            for (int ms = 0; ms < 2; ms++) {
                #pragma unroll
                for (int ns = 0; ns < 8; ns++) {
                    const uint32_t* BB = &bv[ns >> 1][(ns & 1) * 2];
                    MMA(acc[ms][ns], av[ms], BB[0], BB[1]);
                }
            }
        }
    }

    const int mrow = mtile * 128 + wm * 32;
    const int ncol = nt * 128 + wn * 64;
    #pragma unroll
    for (int ms = 0; ms < 2; ms++) {
        const int r0 = mrow + ms * 16 + (lane >> 2);
        const int r1 = r0 + 8;
        #pragma unroll
        for (int ns = 0; ns < 8; ns++) {
            const int c = ncol + ns * 8 + (lane & 3) * 2;
            if (r0 < NROWS)
                *(float2*)(y + (size_t)r0 * D_ + c) = make_float2(acc[ms][ns][0], acc[ms][ns][1]);
            if (r1 < NROWS)
                *(float2*)(y + (size_t)r1 * D_ + c) = make_float2(acc[ms][ns][2], acc[ms][ns][3]);
        }
    }
}

// ---------------- final: bias + residual + LN + exact GELU -> out ------------
__global__ __launch_bounds__(256)
void ln_kernel(const float* __restrict__ y,
               const float* __restrict__ res,
               float* __restrict__ dst,
               const float* __restrict__ gamma, const float* __restrict__ beta,
               const float* __restrict__ bias)
{
    int row = blockIdx.x * 8 + (threadIdx.x >> 5);
    int lane = threadIdx.x & 31;
    if (row >= NROWS) return;
    int g = row / N_, n = row - g * N_;
    int bb = g / T_, tt = g - bb * T_;
    long toff = ((long)(bb * N_ + n) * T_ + tt) * D_;

    const float* rp = res + (long)row * D_;
    float* dp = dst + toff;
    const float* yp = y + (long)row * D_;

    float v[16];
    float sum = 0.0f, sq = 0.0f;
    #pragma unroll
    for (int i = 0; i < 4; i++) {
        int c = lane * 4 + i * 128;
        float4 a = *(const float4*)(yp + c);
        float4 r4 = *(const float4*)(rp + c);
        float4 b4 = *(const float4*)(bias + c);
        float t0 = a.x + b4.x + r4.x, t1 = a.y + b4.y + r4.y;
        float t2 = a.z + b4.z + r4.z, t3 = a.w + b4.w + r4.w;
        v[i*4+0] = t0; v[i*4+1] = t1; v[i*4+2] = t2; v[i*4+3] = t3;
        sum += t0 + t1 + t2 + t3;
        sq = fmaf(t0, t0, sq); sq = fmaf(t1, t1, sq);
        sq = fmaf(t2, t2, sq); sq = fmaf(t3, t3, sq);
    }
    #pragma unroll
    for (int o = 16; o; o >>= 1) {
        sum += __shfl_xor_sync(0xffffffffu, sum, o);
        sq  += __shfl_xor_sync(0xffffffffu, sq, o);
    }
    float mu = sum * (1.0f / D_);
    float var = sq * (1.0f / D_) - mu * mu;
    float rstd = rsqrtf(var + LN_EPS);
    #pragma unroll
    for (int i = 0; i < 4; i++) {
        int c = lane * 4 + i * 128;
        float4 g4 = *(const float4*)(gamma + c);
        float4 be4 = *(const float4*)(beta + c);
        float o0 = fmaf((v[i*4+0] - mu) * rstd, g4.x, be4.x);
        float o1 = fmaf((v[i*4+1] - mu) * rstd, g4.y, be4.y);
        float o2 = fmaf((v[i*4+2] - mu) * rstd, g4.z, be4.z);
        float o3 = fmaf((v[i*4+3] - mu) * rstd, g4.w, be4.w);
        o0 = 0.5f * o0 * (1.0f + erff(o0 * 0.70710678118654752f));
        o1 = 0.5f * o1 * (1.0f + erff(o1 * 0.70710678118654752f));
        o2 = 0.5f * o2 * (1.0f + erff(o2 * 0.70710678118654752f));
        o3 = 0.5f * o3 * (1.0f + erff(o3 * 0.70710678118654752f));
        *(float4*)(dp + c) = make_float4(o0, o1, o2, o3);
    }
}

// ---------------- launch -----------------------------------------------------
extern "C" void kernel_launch(void* const* d_in, const int* in_sizes, int n_in,
                              void* d_out, int out_size)
{
    const float* features  = (const float*)d_in[0];
    const float* adjacency = (const float*)d_in[1];
    const float* edge_w    = (const float*)d_in[2];
    const float* edge_b    = (const float*)d_in[3];
    const float* W         = (const float*)d_in[4];
    const float* bias      = (const float*)d_in[5];
    const float* gamma     = (const float*)d_in[6];
    const float* beta      = (const float*)d_in[7];
    float* out = (float*)d_out;

    unsigned char *av, *bv;
    float *yv, *state;
    cudaGetSymbolAddress((void**)&av, g_a);
    cudaGetSymbolAddress((void**)&bv, g_b);
    cudaGetSymbolAddress((void**)&yv, g_y);
    cudaGetSymbolAddress((void**)&state, g_state);

    cudaFuncSetAttribute(gemm_kernel, cudaFuncAttributeMaxDynamicSharedMemorySize,
                         GEMM_SMEM_DYN);

    adj_kernel<<<NGRAPH, 128>>>(adjacency, edge_w, edge_b);
    wconv_kernel<<<256, 256>>>(W);

    const size_t bl = (size_t)KCHUNKS * NTILES * BTILE_BYTES;

    // layer 0
    mix_kernel<<<NGRAPH, 256>>>(features);
    gemm_kernel<<<MTILES * NTILES, 256, GEMM_SMEM_DYN>>>(av, bv, yv);
    // fused: layer-0 LN/GELU (writes state) + layer-1 mix (writes A tiles)
    lnmix_kernel<<<NGRAPH, 256>>>(yv, features, gamma, beta, bias);
    // layer 1
    gemm_kernel<<<MTILES * NTILES, 256, GEMM_SMEM_DYN>>>(av, bv + bl, yv);
    ln_kernel<<<(NROWS + 7) / 8, 256>>>(yv, state, out,
                                        gamma + D_, beta + D_, bias + D_);
}